// round 10
// baseline (speedup 1.0000x reference)
#include <cuda_runtime.h>
#include <cuda_bf16.h>
#include <cstdint>

// Problem constants
#define BATCH 4
#define SEQ   2048
#define DMODEL 1280
#define NHEAD 16
#define HDIM  80
#define MTOT  (BATCH*SEQ)          // 8192
#define NQKV  (3*NHEAD*HDIM)       // 3840
#define HH    (NHEAD*HDIM)         // 1280

// ---------------------------------------------------------------------------
// Scratch (__device__ globals; no allocation anywhere)
// ---------------------------------------------------------------------------
__device__ float         g_qkv[(size_t)MTOT*NQKV];     // [B*S, 3*H*HD] fp32
__device__ __nv_bfloat16 g_h_hi[(size_t)MTOT*DMODEL];
__device__ __nv_bfloat16 g_h_lo[(size_t)MTOT*DMODEL];
__device__ __nv_bfloat16 g_w1_hi[(size_t)NQKV*DMODEL];
__device__ __nv_bfloat16 g_w1_lo[(size_t)NQKV*DMODEL];
__device__ __nv_bfloat16 g_w2_hi[(size_t)DMODEL*HH];
__device__ __nv_bfloat16 g_w2_lo[(size_t)DMODEL*HH];
__device__ __nv_bfloat16 g_a_hi[(size_t)MTOT*HH];
__device__ __nv_bfloat16 g_a_lo[(size_t)MTOT*HH];
__device__ float         g_scale[HDIM];

// ---------------------------------------------------------------------------
// PTX helpers (plain-sm_103 compatible)
// ---------------------------------------------------------------------------
__device__ __forceinline__ uint32_t s2u(const void* p) {
    uint32_t a;
    asm("{ .reg .u64 t; cvta.to.shared.u64 t, %1; cvt.u32.u64 %0, t; }"
        : "=r"(a) : "l"(p));
    return a;
}

__device__ __forceinline__ void cp_async16(uint32_t saddr, const void* gptr) {
    asm volatile("cp.async.cg.shared.global [%0], [%1], 16;"
                 :: "r"(saddr), "l"(gptr) : "memory");
}
__device__ __forceinline__ void cp_commit() {
    asm volatile("cp.async.commit_group;" ::: "memory");
}
template<int N>
__device__ __forceinline__ void cp_wait() {
    asm volatile("cp.async.wait_group %0;" :: "n"(N) : "memory");
}

__device__ __forceinline__ void ldm_x4(uint32_t* r, uint32_t addr) {
    asm volatile("ldmatrix.sync.aligned.m8n8.x4.shared.b16 {%0,%1,%2,%3}, [%4];"
                 : "=r"(r[0]), "=r"(r[1]), "=r"(r[2]), "=r"(r[3]) : "r"(addr));
}
__device__ __forceinline__ void ldm_x4_t(uint32_t* r, uint32_t addr) {
    asm volatile("ldmatrix.sync.aligned.m8n8.x4.trans.shared.b16 {%0,%1,%2,%3}, [%4];"
                 : "=r"(r[0]), "=r"(r[1]), "=r"(r[2]), "=r"(r[3]) : "r"(addr));
}

__device__ __forceinline__ void mma16816(float* c, const uint32_t* a,
                                         uint32_t b0, uint32_t b1) {
    asm volatile(
        "mma.sync.aligned.m16n8k16.row.col.f32.bf16.bf16.f32 "
        "{%0,%1,%2,%3},{%4,%5,%6,%7},{%8,%9},{%0,%1,%2,%3};"
        : "+f"(c[0]), "+f"(c[1]), "+f"(c[2]), "+f"(c[3])
        : "r"(a[0]), "r"(a[1]), "r"(a[2]), "r"(a[3]), "r"(b0), "r"(b1));
}

// pack two fp32 -> bf16x2 (e0 in low half, e1 in high half)
__device__ __forceinline__ uint32_t packbf(float e0, float e1) {
    uint32_t r;
    asm("cvt.rn.bf16x2.f32 %0, %1, %2;" : "=r"(r) : "f"(e1), "f"(e0));
    return r;
}

// truncation split: x = hi + lo, hi = upper-16-bit bf16 bits, lo fp32 residual
__device__ __forceinline__ void split2(float x, uint32_t& hb, float& lf) {
    uint32_t u = __float_as_uint(x) & 0xffff0000u;
    lf = x - __uint_as_float(u);
    hb = u >> 16;
}

// ---------------------------------------------------------------------------
// per-dim query scale (extra log2e: scores live in log2 domain)
// ---------------------------------------------------------------------------
__global__ void scale_kernel(const float* __restrict__ scaling) {
    int i = threadIdx.x;
    if (i < HDIM) {
        float x = scaling[i];
        float sp = (x > 20.f) ? x : log1pf(expf(x));
        g_scale[i] = sp * 1.442695041f * rsqrtf((float)HDIM) * 1.442695041f;
    }
}

// ---------------------------------------------------------------------------
// fp32 -> bf16 hi/lo split
// ---------------------------------------------------------------------------
__global__ void cvt_split(const float* __restrict__ x,
                          __nv_bfloat16* __restrict__ hi,
                          __nv_bfloat16* __restrict__ lo, int n4) {
    int i = blockIdx.x * blockDim.x + threadIdx.x;
    if (i >= n4) return;
    float4 v = ((const float4*)x)[i];
    __nv_bfloat16 h0 = __float2bfloat16(v.x);
    __nv_bfloat16 h1 = __float2bfloat16(v.y);
    __nv_bfloat16 h2 = __float2bfloat16(v.z);
    __nv_bfloat16 h3 = __float2bfloat16(v.w);
    __nv_bfloat162 hh0; hh0.x = h0; hh0.y = h1;
    __nv_bfloat162 hh1; hh1.x = h2; hh1.y = h3;
    __nv_bfloat162 ll0, ll1;
    ll0.x = __float2bfloat16(v.x - __bfloat162float(h0));
    ll0.y = __float2bfloat16(v.y - __bfloat162float(h1));
    ll1.x = __float2bfloat16(v.z - __bfloat162float(h2));
    ll1.y = __float2bfloat16(v.w - __bfloat162float(h3));
    ((__nv_bfloat162*)hi)[2*i]   = hh0;
    ((__nv_bfloat162*)hi)[2*i+1] = hh1;
    ((__nv_bfloat162*)lo)[2*i]   = ll0;
    ((__nv_bfloat162*)lo)[2*i+1] = ll1;
}

// ---------------------------------------------------------------------------
// HMMA GEMM: C = A*B^T + bias (MODE 0: q-scale)
// CTA tile 256x128, 8 warps as 4(M)x2(N), warp tile 64x64 (32 mma / k16 burst).
// 4-stage cp.async pipeline, one __syncthreads per K-chunk.
// ---------------------------------------------------------------------------
#define GK      DMODEL       // 1280
#define KCH     (GK/32)      // 40
#define NIT     (3*KCH)      // 120
#define A_B     (256*80)     // 20480 bytes A per stage (stride 80)
#define B_B     (128*80)     // 10240 bytes B per stage
#define STG_B   (A_B+B_B)    // 30720
#define GSMEM   (4*STG_B)    // 122880

template<int MODE>
__global__ __launch_bounds__(256)
void mma_gemm(const __nv_bfloat16* __restrict__ Ahi, const __nv_bfloat16* __restrict__ Alo,
              const __nv_bfloat16* __restrict__ Bhi, const __nv_bfloat16* __restrict__ Blo,
              const float* __restrict__ bias, float* __restrict__ dst, int Nld)
{
    extern __shared__ __align__(16) unsigned char dynsm[];

    const int tid  = threadIdx.x;
    const int lane = tid & 31;
    const int wid  = tid >> 5;
    const int wm   = wid >> 1;        // 0..3 -> 64 rows each
    const int wn   = wid & 1;         // 0..1 -> 64 cols each
    const int m0   = blockIdx.y * 256;
    const int n0   = blockIdx.x * 128;

    float acc[4][8][4];
#pragma unroll
    for (int a = 0; a < 4; ++a)
#pragma unroll
        for (int b = 0; b < 8; ++b)
#pragma unroll
            for (int c = 0; c < 4; ++c) acc[a][b][c] = 0.f;

    const int lrow = tid >> 2;        // 0..63
    const int lchk = tid & 3;
    const uint32_t smem_u = s2u(dynsm);

    auto issue = [&](int cc, int stg) {
        const int seg = cc / KCH;
        const int k0  = (cc % KCH) * 32;
        const __nv_bfloat16* Ap = (seg == 1) ? Alo : Ahi;
        const __nv_bfloat16* Bp = (seg == 2) ? Blo : Bhi;
        uint32_t sa = smem_u + stg * STG_B;
        uint32_t sb = sa + A_B;
#pragma unroll
        for (int h = 0; h < 4; ++h) {
            int r = lrow + h * 64;
            cp_async16(sa + r * 80 + lchk * 16,
                       Ap + (size_t)(m0 + r) * GK + k0 + lchk * 8);
        }
#pragma unroll
        for (int h = 0; h < 2; ++h) {
            int r = lrow + h * 64;
            cp_async16(sb + r * 80 + lchk * 16,
                       Bp + (size_t)(n0 + r) * GK + k0 + lchk * 8);
        }
    };

    // prologue: stages 0..2 in flight
#pragma unroll
    for (int s = 0; s < 3; ++s) { issue(s, s); cp_commit(); }

    for (int cc = 0; cc < NIT; ++cc) {
        const int stg = cc & 3;
        cp_wait<2>();
        __syncthreads();
        if (cc + 3 < NIT) issue(cc + 3, (cc + 3) & 3);
        cp_commit();

        uint32_t sa = smem_u + stg * STG_B;
        uint32_t sb = sa + A_B;
#pragma unroll
        for (int ks = 0; ks < 2; ++ks) {
            uint32_t af[4][4];
#pragma unroll
            for (int ms = 0; ms < 4; ++ms) {
                int row  = wm * 64 + ms * 16 + (lane & 15);
                int khal = ks * 16 + (lane >> 4) * 8;
                ldm_x4(af[ms], sa + row * 80 + khal * 2);
            }
            uint32_t bf[4][4];
            const int sel = lane >> 3;
#pragma unroll
            for (int nb = 0; nb < 4; ++nb) {
                int nrow = wn * 64 + nb * 16 + (lane & 7) + (sel >> 1) * 8;
                int khal = ks * 16 + (sel & 1) * 8;
                ldm_x4(bf[nb], sb + nrow * 80 + khal * 2);
            }
#pragma unroll
            for (int ms = 0; ms < 4; ++ms)
#pragma unroll
                for (int ns = 0; ns < 8; ++ns) {
                    const uint32_t* bb = bf[ns >> 1];
                    if (ns & 1) mma16816(acc[ms][ns], af[ms], bb[2], bb[3]);
                    else        mma16816(acc[ms][ns], af[ms], bb[0], bb[1]);
                }
        }
    }

    const int qr = lane >> 2;
    const int qc = lane & 3;
#pragma unroll
    for (int ms = 0; ms < 4; ++ms) {
        int mrow = m0 + wm * 64 + ms * 16 + qr;
#pragma unroll
        for (int ns = 0; ns < 8; ++ns) {
            int ncol = n0 + wn * 64 + ns * 8 + qc * 2;
            float b0 = bias[ncol], b1 = bias[ncol + 1];
            float s0 = 1.f, s1 = 1.f;
            if (MODE == 0 && ncol < HH) {
                int d = ncol % HDIM;
                s0 = g_scale[d];
                s1 = g_scale[d + 1];
            }
            float2 v0, v1;
            v0.x = (acc[ms][ns][0] + b0) * s0;
            v0.y = (acc[ms][ns][1] + b1) * s1;
            v1.x = (acc[ms][ns][2] + b0) * s0;
            v1.y = (acc[ms][ns][3] + b1) * s1;
            *(float2*)&dst[(size_t)mrow * Nld + ncol]       = v0;
            *(float2*)&dst[(size_t)(mrow + 8) * Nld + ncol] = v1;
        }
    }
}

// ---------------------------------------------------------------------------
// exp2 on the FMA pipe (no MUFU); args always <= 0 here
// ---------------------------------------------------------------------------
__device__ __forceinline__ float exp2f_fast(float x) {
    x = fmaxf(x, -126.f);
    float t = rintf(x);
    float f = x - t;
    float p = 1.3333558e-3f;
    p = fmaf(p, f, 9.6181291e-3f);
    p = fmaf(p, f, 5.5504109e-2f);
    p = fmaf(p, f, 2.4022651e-1f);
    p = fmaf(p, f, 6.9314718e-1f);
    p = fmaf(p, f, 1.0f);
    return __int_as_float(__float_as_int(p) + (((int)t) << 23));
}

// ---------------------------------------------------------------------------
// Tensor-core flash attention (causal, log2-domain softmax).
// Register-prefetch of the next K/V tile overlaps LDG with the mma block.
// ---------------------------------------------------------------------------
#define STR 88   // bf16 elements per smem row (176B, conflict-free ldmatrix)

__global__ __launch_bounds__(256)
void flash_tc(const float* __restrict__ qkv,
              __nv_bfloat16* __restrict__ ahi,
              __nv_bfloat16* __restrict__ alo)
{
    __shared__ union {
        struct { __nv_bfloat16 h[128*STR]; __nv_bfloat16 l[128*STR]; } q;
        struct { __nv_bfloat16 kh[64*STR]; __nv_bfloat16 kl[64*STR];
                 __nv_bfloat16 vh[64*STR]; __nv_bfloat16 vl[64*STR]; } kv;
    } sm;

    const int tid  = threadIdx.x;
    const int lane = tid & 31;
    const int wm   = tid >> 5;
    const int qb   = blockIdx.x;
    const int bh   = blockIdx.y;
    const int b    = bh >> 4, h = bh & 15;

    // ---- stage Q (pre-scaled fp32 -> bf16 hi/lo) ----
    {
        int row = tid >> 1, half = tid & 1;
        const float* qp = qkv + (size_t)(b*SEQ + qb*128 + row)*NQKV + h*HDIM + half*40;
        uint32_t* dh = (uint32_t*)&sm.q.h[row*STR + half*40];
        uint32_t* dl = (uint32_t*)&sm.q.l[row*STR + half*40];
#pragma unroll
        for (int i = 0; i < 10; ++i) {
            float4 v = *(const float4*)(qp + i*4);
            uint32_t h0,h1,h2,h3; float l0,l1,l2,l3;
            split2(v.x,h0,l0); split2(v.y,h1,l1);
            split2(v.z,h2,l2); split2(v.w,h3,l3);
            dh[i*2]   = h0 | (h1 << 16);
            dh[i*2+1] = h2 | (h3 << 16);
            dl[i*2]   = packbf(l0, l1);
            dl[i*2+1] = packbf(l2, l3);
        }
    }
    __syncthreads();

    uint32_t QH[5][4], QL[5][4];
    {
        int r = wm*16 + (lane & 15);
        int ko = (lane >> 4) * 8;
#pragma unroll
        for (int kf = 0; kf < 5; ++kf) {
            ldm_x4(QH[kf], s2u(&sm.q.h[r*STR + kf*16 + ko]));
            ldm_x4(QL[kf], s2u(&sm.q.l[r*STR + kf*16 + ko]));
        }
    }
    __syncthreads();   // done with q region before kv overwrites it

    float O[10][4];
#pragma unroll
    for (int i = 0; i < 10; ++i)
#pragma unroll
        for (int j = 0; j < 4; ++j) O[i][j] = 0.f;
    float m0 = -1e30f, m1 = -1e30f, l0 = 0.f, l1 = 0.f;

    const int ntiles = qb*2 + 2;
    const int qrow = qb*128 + wm*16 + (lane >> 2);   // row0; row1 = qrow+8

    const int ldr = tid >> 2, ldq = tid & 3;
    const float* kb0 = qkv + (size_t)b*SEQ*NQKV + HH + h*HDIM + ldq*20;

    float4 kreg[5], vreg[5];
    {   // prefetch tile 0
        const float* kp = kb0 + (size_t)ldr * NQKV;
        const float* vp = kp + HH;
#pragma unroll
        for (int i = 0; i < 5; ++i) {
            kreg[i] = *(const float4*)(kp + i*4);
            vreg[i] = *(const float4*)(vp + i*4);
        }
    }

    for (int t = 0; t < ntiles; ++t) {
        // ---- convert + store prefetched K/V tile (hi/lo) ----
        {
            uint32_t* kh = (uint32_t*)&sm.kv.kh[ldr*STR + ldq*20];
            uint32_t* kl = (uint32_t*)&sm.kv.kl[ldr*STR + ldq*20];
            uint32_t* vh = (uint32_t*)&sm.kv.vh[ldr*STR + ldq*20];
            uint32_t* vl = (uint32_t*)&sm.kv.vl[ldr*STR + ldq*20];
#pragma unroll
            for (int i = 0; i < 5; ++i) {
                uint32_t h0,h1,h2,h3; float f0,f1,f2,f3;
                split2(kreg[i].x,h0,f0); split2(kreg[i].y,h1,f1);
                split2(kreg[i].z,h2,f2); split2(kreg[i].w,h3,f3);
                kh[i*2]   = h0 | (h1 << 16);
                kh[i*2+1] = h2 | (h3 << 16);
                kl[i*2]   = packbf(f0, f1);
                kl[i*2+1] = packbf(f2, f3);
                split2(vreg[i].x,h0,f0); split2(vreg[i].y,h1,f1);
                split2(vreg[i].z,h2,f2); split2(vreg[i].w,h3,f3);
                vh[i*2]   = h0 | (h1 << 16);
                vh[i*2+1] = h2 | (h3 << 16);
                vl[i*2]   = packbf(f0, f1);
                vl[i*2+1] = packbf(f2, f3);
            }
        }
        __syncthreads();

        // ---- prefetch next tile while mma block runs ----
        if (t + 1 < ntiles) {
            const float* kp = kb0 + (size_t)((t+1)*64 + ldr) * NQKV;
            const float* vp = kp + HH;
#pragma unroll
            for (int i = 0; i < 5; ++i) {
                kreg[i] = *(const float4*)(kp + i*4);
                vreg[i] = *(const float4*)(vp + i*4);
            }
        }

        const bool active = (t*64) <= (qb*128 + wm*16 + 15);
        if (active) {
            float S[8][4];
#pragma unroll
            for (int i = 0; i < 8; ++i)
#pragma unroll
                for (int j = 0; j < 4; ++j) S[i][j] = 0.f;

            // ---- S = Q K^T (hh + lh + hl) ----
#pragma unroll
            for (int kf = 0; kf < 5; ++kf) {
                const int sel  = lane >> 3;
                const int koff = kf*16 + (sel & 1)*8;
#pragma unroll
                for (int g = 0; g < 4; ++g) {
                    uint32_t bh_[4], bl_[4];
                    int krow = g*16 + (lane & 7) + (sel >> 1)*8;
                    ldm_x4(bh_, s2u(&sm.kv.kh[krow*STR + koff]));
                    ldm_x4(bl_, s2u(&sm.kv.kl[krow*STR + koff]));
                    mma16816(S[2*g],   QH[kf], bh_[0], bh_[1]);
                    mma16816(S[2*g+1], QH[kf], bh_[2], bh_[3]);
                    mma16816(S[2*g],   QL[kf], bh_[0], bh_[1]);
                    mma16816(S[2*g+1], QL[kf], bh_[2], bh_[3]);
                    mma16816(S[2*g],   QH[kf], bl_[0], bl_[1]);
                    mma16816(S[2*g+1], QH[kf], bl_[2], bl_[3]);
                }
            }

            // ---- causal mask (diagonal tiles only) ----
            if (t*64 + 63 > qb*128 + wm*16) {
#pragma unroll
                for (int nt = 0; nt < 8; ++nt) {
                    int j = t*64 + nt*8 + (lane & 3)*2;
                    if (j     > qrow)     S[nt][0] = -1e30f;
                    if (j + 1 > qrow)     S[nt][1] = -1e30f;
                    if (j     > qrow + 8) S[nt][2] = -1e30f;
                    if (j + 1 > qrow + 8) S[nt][3] = -1e30f;
                }
            }

            // ---- online softmax ----
            float rm0 = -1e30f, rm1 = -1e30f;
#pragma unroll
            for (int nt = 0; nt < 8; ++nt) {
                rm0 = fmaxf(rm0, fmaxf(S[nt][0], S[nt][1]));
                rm1 = fmaxf(rm1, fmaxf(S[nt][2], S[nt][3]));
            }
            rm0 = fmaxf(rm0, __shfl_xor_sync(0xffffffffu, rm0, 1));
            rm0 = fmaxf(rm0, __shfl_xor_sync(0xffffffffu, rm0, 2));
            rm1 = fmaxf(rm1, __shfl_xor_sync(0xffffffffu, rm1, 1));
            rm1 = fmaxf(rm1, __shfl_xor_sync(0xffffffffu, rm1, 2));

            float nm0 = fmaxf(m0, rm0), nm1 = fmaxf(m1, rm1);
            float a0 = exp2f_fast(m0 - nm0), a1 = exp2f_fast(m1 - nm1);
            m0 = nm0; m1 = nm1;
#pragma unroll
            for (int nt = 0; nt < 10; ++nt) {
                O[nt][0] *= a0; O[nt][1] *= a0;
                O[nt][2] *= a1; O[nt][3] *= a1;
            }
            float s0 = 0.f, s1 = 0.f;
#pragma unroll
            for (int nt = 0; nt < 8; ++nt) {
                S[nt][0] = exp2f_fast(S[nt][0] - nm0); s0 += S[nt][0];
                S[nt][1] = exp2f_fast(S[nt][1] - nm0); s0 += S[nt][1];
                S[nt][2] = exp2f_fast(S[nt][2] - nm1); s1 += S[nt][2];
                S[nt][3] = exp2f_fast(S[nt][3] - nm1); s1 += S[nt][3];
            }
            s0 += __shfl_xor_sync(0xffffffffu, s0, 1);
            s0 += __shfl_xor_sync(0xffffffffu, s0, 2);
            s1 += __shfl_xor_sync(0xffffffffu, s1, 1);
            s1 += __shfl_xor_sync(0xffffffffu, s1, 2);
            l0 = l0*a0 + s0;
            l1 = l1*a1 + s1;

            // ---- P -> A fragments (hi/lo, in-register) ----
            uint32_t PH[4][4], PL[4][4];
#pragma unroll
            for (int g = 0; g < 4; ++g) {
                uint32_t hb[8]; float lf[8];
                split2(S[2*g][0], hb[0], lf[0]);  split2(S[2*g][1], hb[1], lf[1]);
                split2(S[2*g][2], hb[2], lf[2]);  split2(S[2*g][3], hb[3], lf[3]);
                split2(S[2*g+1][0], hb[4], lf[4]); split2(S[2*g+1][1], hb[5], lf[5]);
                split2(S[2*g+1][2], hb[6], lf[6]); split2(S[2*g+1][3], hb[7], lf[7]);
                PH[g][0] = hb[0] | (hb[1] << 16);
                PH[g][1] = hb[2] | (hb[3] << 16);
                PH[g][2] = hb[4] | (hb[5] << 16);
                PH[g][3] = hb[6] | (hb[7] << 16);
                PL[g][0] = packbf(lf[0], lf[1]);
                PL[g][1] = packbf(lf[2], lf[3]);
                PL[g][2] = packbf(lf[4], lf[5]);
                PL[g][3] = packbf(lf[6], lf[7]);
            }

            // ---- O += PH*VH + PL*VH + PH*VL ----
            const int sel = lane >> 3;
#pragma unroll
            for (int g = 0; g < 4; ++g) {
                int krow = g*16 + (lane & 7) + (sel & 1)*8;
#pragma unroll
                for (int np = 0; np < 5; ++np) {
                    uint32_t bv[4], bw[4];
                    int noff = np*16 + (sel >> 1)*8;
                    ldm_x4_t(bv, s2u(&sm.kv.vh[krow*STR + noff]));
                    ldm_x4_t(bw, s2u(&sm.kv.vl[krow*STR + noff]));
                    mma16816(O[2*np],   PH[g], bv[0], bv[1]);
                    mma16816(O[2*np],   PL[g], bv[0], bv[1]);
                    mma16816(O[2*np],   PH[g], bw[0], bw[1]);
                    mma16816(O[2*np+1], PH[g], bv[2], bv[3]);
                    mma16816(O[2*np+1], PL[g], bv[2], bv[3]);
                    mma16816(O[2*np+1], PH[g], bw[2], bw[3]);
                }
            }
        }
        __syncthreads();
    }

    // ---- epilogue: normalize, write bf16 hi/lo ----
    const float i0 = 1.f / l0, i1 = 1.f / l1;
    const size_t base0 = (size_t)(b*SEQ + qrow) * HH + h * HDIM;
    const size_t base1 = base0 + (size_t)8 * HH;
#pragma unroll
    for (int nt = 0; nt < 10; ++nt) {
        int d = nt*8 + (lane & 3)*2;
        {
            float v0 = O[nt][0]*i0, v1 = O[nt][1]*i0;
            uint32_t h0,h1; float f0,f1;
            split2(v0,h0,f0); split2(v1,h1,f1);
            *(uint32_t*)&ahi[base0 + d] = h0 | (h1 << 16);
            *(uint32_t*)&alo[base0 + d] = packbf(f0, f1);
        }
        {
            float v0 = O[nt][2]*i1, v1 = O[nt][3]*i1;
            uint32_t h0,h1; float f0,f1;
            split2(v0,h0,f0); split2(v1,h1,f1);
            *(uint32_t*)&ahi[base1 + d] = h0 | (h1 << 16);
            *(uint32_t*)&alo[base1 + d] = packbf(f0, f1);
        }
    }
}

// ---------------------------------------------------------------------------
// Launch
// ---------------------------------------------------------------------------
extern "C" void kernel_launch(void* const* d_in, const int* in_sizes, int n_in,
                              void* d_out, int out_size)
{
    const float* hidden  = (const float*)d_in[0];
    // d_in[1] = attention_mask: exact additive causal mask; implemented directly.
    const float* scaling = (const float*)d_in[2];
    const float* qkv_w   = (const float*)d_in[3];
    const float* qkv_b   = (const float*)d_in[4];
    const float* o_w     = (const float*)d_in[5];
    const float* o_b     = (const float*)d_in[6];
    float* out = (float*)d_out;

    float *qkv; __nv_bfloat16 *hhi, *hlo, *w1h, *w1l, *w2h, *w2l, *ahi, *alo;
    cudaGetSymbolAddress((void**)&qkv, g_qkv);
    cudaGetSymbolAddress((void**)&hhi, g_h_hi);
    cudaGetSymbolAddress((void**)&hlo, g_h_lo);
    cudaGetSymbolAddress((void**)&w1h, g_w1_hi);
    cudaGetSymbolAddress((void**)&w1l, g_w1_lo);
    cudaGetSymbolAddress((void**)&w2h, g_w2_hi);
    cudaGetSymbolAddress((void**)&w2l, g_w2_lo);
    cudaGetSymbolAddress((void**)&ahi, g_a_hi);
    cudaGetSymbolAddress((void**)&alo, g_a_lo);

    cudaFuncSetAttribute(mma_gemm<0>, cudaFuncAttributeMaxDynamicSharedMemorySize, GSMEM);
    cudaFuncSetAttribute(mma_gemm<1>, cudaFuncAttributeMaxDynamicSharedMemorySize, GSMEM);

    scale_kernel<<<1, 128>>>(scaling);

    {   // hidden -> hi/lo
        int n4 = (MTOT * DMODEL) / 4;
        cvt_split<<<(n4 + 255) / 256, 256>>>(hidden, hhi, hlo, n4);
    }
    {   // qkv_w -> hi/lo
        int n4 = (NQKV * DMODEL) / 4;
        cvt_split<<<(n4 + 255) / 256, 256>>>(qkv_w, w1h, w1l, n4);
    }

    // QKV projection: [8192,1280] @ [3840,1280]^T -> g_qkv (bias + q-scale)
    mma_gemm<0><<<dim3(NQKV / 128, MTOT / 256), 256, GSMEM>>>(
        hhi, hlo, w1h, w1l, qkv_b, qkv, NQKV);

    // Tensor-core flash attention -> bf16 hi/lo
    flash_tc<<<dim3(SEQ / 128, BATCH * NHEAD), 256>>>(qkv, ahi, alo);

    {   // o_w -> hi/lo
        int n4 = (DMODEL * HH) / 4;
        cvt_split<<<(n4 + 255) / 256, 256>>>(o_w, w2h, w2l, n4);
    }

    // Output projection: [8192,1280] @ [1280,1280]^T -> out (bias)
    mma_gemm<1><<<dim3(DMODEL / 128, MTOT / 256), 256, GSMEM>>>(
        ahi, alo, w2h, w2l, o_b, out, DMODEL);
}

// round 11
// speedup vs baseline: 1.0933x; 1.0933x over previous
#include <cuda_runtime.h>
#include <cuda_bf16.h>
#include <cstdint>

// Problem constants
#define BATCH 4
#define SEQ   2048
#define DMODEL 1280
#define NHEAD 16
#define HDIM  80
#define MTOT  (BATCH*SEQ)          // 8192
#define NQKV  (3*NHEAD*HDIM)       // 3840
#define HH    (NHEAD*HDIM)         // 1280

// ---------------------------------------------------------------------------
// Scratch (__device__ globals; no allocation anywhere)
// ---------------------------------------------------------------------------
__device__ float         g_qkv[(size_t)MTOT*NQKV];     // [B*S, 3*H*HD] fp32
__device__ __nv_bfloat16 g_h_hi[(size_t)MTOT*DMODEL];
__device__ __nv_bfloat16 g_h_lo[(size_t)MTOT*DMODEL];
__device__ __nv_bfloat16 g_w1_hi[(size_t)NQKV*DMODEL];
__device__ __nv_bfloat16 g_w1_lo[(size_t)NQKV*DMODEL];
__device__ __nv_bfloat16 g_w2_hi[(size_t)DMODEL*HH];
__device__ __nv_bfloat16 g_w2_lo[(size_t)DMODEL*HH];
__device__ __nv_bfloat16 g_a_hi[(size_t)MTOT*HH];
__device__ __nv_bfloat16 g_a_lo[(size_t)MTOT*HH];
__device__ float         g_scale[HDIM];

// ---------------------------------------------------------------------------
// PTX helpers (plain-sm_103 compatible)
// ---------------------------------------------------------------------------
__device__ __forceinline__ uint32_t s2u(const void* p) {
    uint32_t a;
    asm("{ .reg .u64 t; cvta.to.shared.u64 t, %1; cvt.u32.u64 %0, t; }"
        : "=r"(a) : "l"(p));
    return a;
}

__device__ __forceinline__ void cp_async16(uint32_t saddr, const void* gptr) {
    asm volatile("cp.async.cg.shared.global [%0], [%1], 16;"
                 :: "r"(saddr), "l"(gptr) : "memory");
}
__device__ __forceinline__ void cp_commit() {
    asm volatile("cp.async.commit_group;" ::: "memory");
}
template<int N>
__device__ __forceinline__ void cp_wait() {
    asm volatile("cp.async.wait_group %0;" :: "n"(N) : "memory");
}

__device__ __forceinline__ void ldm_x4(uint32_t* r, uint32_t addr) {
    asm volatile("ldmatrix.sync.aligned.m8n8.x4.shared.b16 {%0,%1,%2,%3}, [%4];"
                 : "=r"(r[0]), "=r"(r[1]), "=r"(r[2]), "=r"(r[3]) : "r"(addr));
}
__device__ __forceinline__ void ldm_x4_t(uint32_t* r, uint32_t addr) {
    asm volatile("ldmatrix.sync.aligned.m8n8.x4.trans.shared.b16 {%0,%1,%2,%3}, [%4];"
                 : "=r"(r[0]), "=r"(r[1]), "=r"(r[2]), "=r"(r[3]) : "r"(addr));
}

__device__ __forceinline__ void mma16816(float* c, const uint32_t* a,
                                         uint32_t b0, uint32_t b1) {
    asm volatile(
        "mma.sync.aligned.m16n8k16.row.col.f32.bf16.bf16.f32 "
        "{%0,%1,%2,%3},{%4,%5,%6,%7},{%8,%9},{%0,%1,%2,%3};"
        : "+f"(c[0]), "+f"(c[1]), "+f"(c[2]), "+f"(c[3])
        : "r"(a[0]), "r"(a[1]), "r"(a[2]), "r"(a[3]), "r"(b0), "r"(b1));
}

// pack two fp32 -> bf16x2 (e0 in low half, e1 in high half)
__device__ __forceinline__ uint32_t packbf(float e0, float e1) {
    uint32_t r;
    asm("cvt.rn.bf16x2.f32 %0, %1, %2;" : "=r"(r) : "f"(e1), "f"(e0));
    return r;
}

// truncation split: x = hi + lo, hi = upper-16-bit bf16 bits, lo fp32 residual
__device__ __forceinline__ void split2(float x, uint32_t& hb, float& lf) {
    uint32_t u = __float_as_uint(x) & 0xffff0000u;
    lf = x - __uint_as_float(u);
    hb = u >> 16;
}

// ---------------------------------------------------------------------------
// per-dim query scale (extra log2e: scores live in log2 domain)
// ---------------------------------------------------------------------------
__global__ void scale_kernel(const float* __restrict__ scaling) {
    int i = threadIdx.x;
    if (i < HDIM) {
        float x = scaling[i];
        float sp = (x > 20.f) ? x : log1pf(expf(x));
        g_scale[i] = sp * 1.442695041f * rsqrtf((float)HDIM) * 1.442695041f;
    }
}

// ---------------------------------------------------------------------------
// fp32 -> bf16 hi/lo split
// ---------------------------------------------------------------------------
__global__ void cvt_split(const float* __restrict__ x,
                          __nv_bfloat16* __restrict__ hi,
                          __nv_bfloat16* __restrict__ lo, int n4) {
    int i = blockIdx.x * blockDim.x + threadIdx.x;
    if (i >= n4) return;
    float4 v = ((const float4*)x)[i];
    __nv_bfloat16 h0 = __float2bfloat16(v.x);
    __nv_bfloat16 h1 = __float2bfloat16(v.y);
    __nv_bfloat16 h2 = __float2bfloat16(v.z);
    __nv_bfloat16 h3 = __float2bfloat16(v.w);
    __nv_bfloat162 hh0; hh0.x = h0; hh0.y = h1;
    __nv_bfloat162 hh1; hh1.x = h2; hh1.y = h3;
    __nv_bfloat162 ll0, ll1;
    ll0.x = __float2bfloat16(v.x - __bfloat162float(h0));
    ll0.y = __float2bfloat16(v.y - __bfloat162float(h1));
    ll1.x = __float2bfloat16(v.z - __bfloat162float(h2));
    ll1.y = __float2bfloat16(v.w - __bfloat162float(h3));
    ((__nv_bfloat162*)hi)[2*i]   = hh0;
    ((__nv_bfloat162*)hi)[2*i+1] = hh1;
    ((__nv_bfloat162*)lo)[2*i]   = ll0;
    ((__nv_bfloat162*)lo)[2*i+1] = ll1;
}

// ---------------------------------------------------------------------------
// HMMA GEMM: C = A*B^T + bias (MODE 0: q-scale)
// CTA tile 128x128, 4 warps (128 thr) as 2(M)x2(N); warp tile 64x64
// (8 LDSM.x4 -> 32 mma per k16). 4-stage cp.async pipeline, 2 CTAs/SM.
// ---------------------------------------------------------------------------
#define GK      DMODEL       // 1280
#define KCH     (GK/32)      // 40
#define NIT     (3*KCH)      // 120
#define A_B     (128*80)     // 10240 bytes A per stage (stride 80)
#define B_B     (128*80)     // 10240 bytes B per stage
#define STG_B   (A_B+B_B)    // 20480
#define GSMEM   (4*STG_B)    // 81920

template<int MODE>
__global__ __launch_bounds__(128)
void mma_gemm(const __nv_bfloat16* __restrict__ Ahi, const __nv_bfloat16* __restrict__ Alo,
              const __nv_bfloat16* __restrict__ Bhi, const __nv_bfloat16* __restrict__ Blo,
              const float* __restrict__ bias, float* __restrict__ dst, int Nld)
{
    extern __shared__ __align__(16) unsigned char dynsm[];

    const int tid  = threadIdx.x;
    const int lane = tid & 31;
    const int wid  = tid >> 5;
    const int wm   = wid >> 1;        // 0..1 -> 64 rows each
    const int wn   = wid & 1;         // 0..1 -> 64 cols each
    const int m0   = blockIdx.y * 128;
    const int n0   = blockIdx.x * 128;

    float acc[4][8][4];
#pragma unroll
    for (int a = 0; a < 4; ++a)
#pragma unroll
        for (int b = 0; b < 8; ++b)
#pragma unroll
            for (int c = 0; c < 4; ++c) acc[a][b][c] = 0.f;

    const int lrow = tid >> 2;        // 0..31
    const int lchk = tid & 3;         // 16B chunk within 64B row
    const uint32_t smem_u = s2u(dynsm);

    auto issue = [&](int cc, int stg) {
        const int seg = cc / KCH;
        const int k0  = (cc % KCH) * 32;
        const __nv_bfloat16* Ap = (seg == 1) ? Alo : Ahi;
        const __nv_bfloat16* Bp = (seg == 2) ? Blo : Bhi;
        uint32_t sa = smem_u + stg * STG_B;
        uint32_t sb = sa + A_B;
#pragma unroll
        for (int h = 0; h < 4; ++h) {
            int r = lrow + h * 32;
            cp_async16(sa + r * 80 + lchk * 16,
                       Ap + (size_t)(m0 + r) * GK + k0 + lchk * 8);
            cp_async16(sb + r * 80 + lchk * 16,
                       Bp + (size_t)(n0 + r) * GK + k0 + lchk * 8);
        }
    };

    // prologue: stages 0..2 in flight
#pragma unroll
    for (int s = 0; s < 3; ++s) { issue(s, s); cp_commit(); }

    for (int cc = 0; cc < NIT; ++cc) {
        const int stg = cc & 3;
        cp_wait<2>();
        __syncthreads();
        if (cc + 3 < NIT) issue(cc + 3, (cc + 3) & 3);
        cp_commit();

        uint32_t sa = smem_u + stg * STG_B;
        uint32_t sb = sa + A_B;
#pragma unroll
        for (int ks = 0; ks < 2; ++ks) {
            uint32_t af[4][4];
#pragma unroll
            for (int ms = 0; ms < 4; ++ms) {
                int row  = wm * 64 + ms * 16 + (lane & 15);
                int khal = ks * 16 + (lane >> 4) * 8;
                ldm_x4(af[ms], sa + row * 80 + khal * 2);
            }
            uint32_t bf[4][4];
            const int sel = lane >> 3;
#pragma unroll
            for (int nb = 0; nb < 4; ++nb) {
                int nrow = wn * 64 + nb * 16 + (lane & 7) + (sel >> 1) * 8;
                int khal = ks * 16 + (sel & 1) * 8;
                ldm_x4(bf[nb], sb + nrow * 80 + khal * 2);
            }
#pragma unroll
            for (int ms = 0; ms < 4; ++ms)
#pragma unroll
                for (int ns = 0; ns < 8; ++ns) {
                    const uint32_t* bb = bf[ns >> 1];
                    if (ns & 1) mma16816(acc[ms][ns], af[ms], bb[2], bb[3]);
                    else        mma16816(acc[ms][ns], af[ms], bb[0], bb[1]);
                }
        }
    }

    const int qr = lane >> 2;
    const int qc = lane & 3;
#pragma unroll
    for (int ms = 0; ms < 4; ++ms) {
        int mrow = m0 + wm * 64 + ms * 16 + qr;
#pragma unroll
        for (int ns = 0; ns < 8; ++ns) {
            int ncol = n0 + wn * 64 + ns * 8 + qc * 2;
            float b0 = bias[ncol], b1 = bias[ncol + 1];
            float s0 = 1.f, s1 = 1.f;
            if (MODE == 0 && ncol < HH) {
                int d = ncol % HDIM;
                s0 = g_scale[d];
                s1 = g_scale[d + 1];
            }
            float2 v0, v1;
            v0.x = (acc[ms][ns][0] + b0) * s0;
            v0.y = (acc[ms][ns][1] + b1) * s1;
            v1.x = (acc[ms][ns][2] + b0) * s0;
            v1.y = (acc[ms][ns][3] + b1) * s1;
            *(float2*)&dst[(size_t)mrow * Nld + ncol]       = v0;
            *(float2*)&dst[(size_t)(mrow + 8) * Nld + ncol] = v1;
        }
    }
}

// ---------------------------------------------------------------------------
// exp2 on the FMA pipe (no MUFU); args always <= 0 here
// ---------------------------------------------------------------------------
__device__ __forceinline__ float exp2f_fast(float x) {
    x = fmaxf(x, -126.f);
    float t = rintf(x);
    float f = x - t;
    float p = 1.3333558e-3f;
    p = fmaf(p, f, 9.6181291e-3f);
    p = fmaf(p, f, 5.5504109e-2f);
    p = fmaf(p, f, 2.4022651e-1f);
    p = fmaf(p, f, 6.9314718e-1f);
    p = fmaf(p, f, 1.0f);
    return __int_as_float(__float_as_int(p) + (((int)t) << 23));
}

// ---------------------------------------------------------------------------
// Tensor-core flash attention (causal, log2-domain softmax).
// Register-prefetch of the next K/V tile overlaps LDG with the mma block.
// ---------------------------------------------------------------------------
#define STR 88   // bf16 elements per smem row (176B, conflict-free ldmatrix)

__global__ __launch_bounds__(256)
void flash_tc(const float* __restrict__ qkv,
              __nv_bfloat16* __restrict__ ahi,
              __nv_bfloat16* __restrict__ alo)
{
    __shared__ union {
        struct { __nv_bfloat16 h[128*STR]; __nv_bfloat16 l[128*STR]; } q;
        struct { __nv_bfloat16 kh[64*STR]; __nv_bfloat16 kl[64*STR];
                 __nv_bfloat16 vh[64*STR]; __nv_bfloat16 vl[64*STR]; } kv;
    } sm;

    const int tid  = threadIdx.x;
    const int lane = tid & 31;
    const int wm   = tid >> 5;
    const int qb   = blockIdx.x;
    const int bh   = blockIdx.y;
    const int b    = bh >> 4, h = bh & 15;

    // ---- stage Q (pre-scaled fp32 -> bf16 hi/lo) ----
    {
        int row = tid >> 1, half = tid & 1;
        const float* qp = qkv + (size_t)(b*SEQ + qb*128 + row)*NQKV + h*HDIM + half*40;
        uint32_t* dh = (uint32_t*)&sm.q.h[row*STR + half*40];
        uint32_t* dl = (uint32_t*)&sm.q.l[row*STR + half*40];
#pragma unroll
        for (int i = 0; i < 10; ++i) {
            float4 v = *(const float4*)(qp + i*4);
            uint32_t h0,h1,h2,h3; float l0,l1,l2,l3;
            split2(v.x,h0,l0); split2(v.y,h1,l1);
            split2(v.z,h2,l2); split2(v.w,h3,l3);
            dh[i*2]   = h0 | (h1 << 16);
            dh[i*2+1] = h2 | (h3 << 16);
            dl[i*2]   = packbf(l0, l1);
            dl[i*2+1] = packbf(l2, l3);
        }
    }
    __syncthreads();

    uint32_t QH[5][4], QL[5][4];
    {
        int r = wm*16 + (lane & 15);
        int ko = (lane >> 4) * 8;
#pragma unroll
        for (int kf = 0; kf < 5; ++kf) {
            ldm_x4(QH[kf], s2u(&sm.q.h[r*STR + kf*16 + ko]));
            ldm_x4(QL[kf], s2u(&sm.q.l[r*STR + kf*16 + ko]));
        }
    }
    __syncthreads();   // done with q region before kv overwrites it

    float O[10][4];
#pragma unroll
    for (int i = 0; i < 10; ++i)
#pragma unroll
        for (int j = 0; j < 4; ++j) O[i][j] = 0.f;
    float m0 = -1e30f, m1 = -1e30f, l0 = 0.f, l1 = 0.f;

    const int ntiles = qb*2 + 2;
    const int qrow = qb*128 + wm*16 + (lane >> 2);   // row0; row1 = qrow+8

    const int ldr = tid >> 2, ldq = tid & 3;
    const float* kb0 = qkv + (size_t)b*SEQ*NQKV + HH + h*HDIM + ldq*20;

    float4 kreg[5], vreg[5];
    {   // prefetch tile 0
        const float* kp = kb0 + (size_t)ldr * NQKV;
        const float* vp = kp + HH;
#pragma unroll
        for (int i = 0; i < 5; ++i) {
            kreg[i] = *(const float4*)(kp + i*4);
            vreg[i] = *(const float4*)(vp + i*4);
        }
    }

    for (int t = 0; t < ntiles; ++t) {
        // ---- convert + store prefetched K/V tile (hi/lo) ----
        {
            uint32_t* kh = (uint32_t*)&sm.kv.kh[ldr*STR + ldq*20];
            uint32_t* kl = (uint32_t*)&sm.kv.kl[ldr*STR + ldq*20];
            uint32_t* vh = (uint32_t*)&sm.kv.vh[ldr*STR + ldq*20];
            uint32_t* vl = (uint32_t*)&sm.kv.vl[ldr*STR + ldq*20];
#pragma unroll
            for (int i = 0; i < 5; ++i) {
                uint32_t h0,h1,h2,h3; float f0,f1,f2,f3;
                split2(kreg[i].x,h0,f0); split2(kreg[i].y,h1,f1);
                split2(kreg[i].z,h2,f2); split2(kreg[i].w,h3,f3);
                kh[i*2]   = h0 | (h1 << 16);
                kh[i*2+1] = h2 | (h3 << 16);
                kl[i*2]   = packbf(f0, f1);
                kl[i*2+1] = packbf(f2, f3);
                split2(vreg[i].x,h0,f0); split2(vreg[i].y,h1,f1);
                split2(vreg[i].z,h2,f2); split2(vreg[i].w,h3,f3);
                vh[i*2]   = h0 | (h1 << 16);
                vh[i*2+1] = h2 | (h3 << 16);
                vl[i*2]   = packbf(f0, f1);
                vl[i*2+1] = packbf(f2, f3);
            }
        }
        __syncthreads();

        // ---- prefetch next tile while mma block runs ----
        if (t + 1 < ntiles) {
            const float* kp = kb0 + (size_t)((t+1)*64 + ldr) * NQKV;
            const float* vp = kp + HH;
#pragma unroll
            for (int i = 0; i < 5; ++i) {
                kreg[i] = *(const float4*)(kp + i*4);
                vreg[i] = *(const float4*)(vp + i*4);
            }
        }

        const bool active = (t*64) <= (qb*128 + wm*16 + 15);
        if (active) {
            float S[8][4];
#pragma unroll
            for (int i = 0; i < 8; ++i)
#pragma unroll
                for (int j = 0; j < 4; ++j) S[i][j] = 0.f;

            // ---- S = Q K^T (hh + lh + hl) ----
#pragma unroll
            for (int kf = 0; kf < 5; ++kf) {
                const int sel  = lane >> 3;
                const int koff = kf*16 + (sel & 1)*8;
#pragma unroll
                for (int g = 0; g < 4; ++g) {
                    uint32_t bh_[4], bl_[4];
                    int krow = g*16 + (lane & 7) + (sel >> 1)*8;
                    ldm_x4(bh_, s2u(&sm.kv.kh[krow*STR + koff]));
                    ldm_x4(bl_, s2u(&sm.kv.kl[krow*STR + koff]));
                    mma16816(S[2*g],   QH[kf], bh_[0], bh_[1]);
                    mma16816(S[2*g+1], QH[kf], bh_[2], bh_[3]);
                    mma16816(S[2*g],   QL[kf], bh_[0], bh_[1]);
                    mma16816(S[2*g+1], QL[kf], bh_[2], bh_[3]);
                    mma16816(S[2*g],   QH[kf], bl_[0], bl_[1]);
                    mma16816(S[2*g+1], QH[kf], bl_[2], bl_[3]);
                }
            }

            // ---- causal mask (diagonal tiles only) ----
            if (t*64 + 63 > qb*128 + wm*16) {
#pragma unroll
                for (int nt = 0; nt < 8; ++nt) {
                    int j = t*64 + nt*8 + (lane & 3)*2;
                    if (j     > qrow)     S[nt][0] = -1e30f;
                    if (j + 1 > qrow)     S[nt][1] = -1e30f;
                    if (j     > qrow + 8) S[nt][2] = -1e30f;
                    if (j + 1 > qrow + 8) S[nt][3] = -1e30f;
                }
            }

            // ---- online softmax ----
            float rm0 = -1e30f, rm1 = -1e30f;
#pragma unroll
            for (int nt = 0; nt < 8; ++nt) {
                rm0 = fmaxf(rm0, fmaxf(S[nt][0], S[nt][1]));
                rm1 = fmaxf(rm1, fmaxf(S[nt][2], S[nt][3]));
            }
            rm0 = fmaxf(rm0, __shfl_xor_sync(0xffffffffu, rm0, 1));
            rm0 = fmaxf(rm0, __shfl_xor_sync(0xffffffffu, rm0, 2));
            rm1 = fmaxf(rm1, __shfl_xor_sync(0xffffffffu, rm1, 1));
            rm1 = fmaxf(rm1, __shfl_xor_sync(0xffffffffu, rm1, 2));

            float nm0 = fmaxf(m0, rm0), nm1 = fmaxf(m1, rm1);
            float a0 = exp2f_fast(m0 - nm0), a1 = exp2f_fast(m1 - nm1);
            m0 = nm0; m1 = nm1;
#pragma unroll
            for (int nt = 0; nt < 10; ++nt) {
                O[nt][0] *= a0; O[nt][1] *= a0;
                O[nt][2] *= a1; O[nt][3] *= a1;
            }
            float s0 = 0.f, s1 = 0.f;
#pragma unroll
            for (int nt = 0; nt < 8; ++nt) {
                S[nt][0] = exp2f_fast(S[nt][0] - nm0); s0 += S[nt][0];
                S[nt][1] = exp2f_fast(S[nt][1] - nm0); s0 += S[nt][1];
                S[nt][2] = exp2f_fast(S[nt][2] - nm1); s1 += S[nt][2];
                S[nt][3] = exp2f_fast(S[nt][3] - nm1); s1 += S[nt][3];
            }
            s0 += __shfl_xor_sync(0xffffffffu, s0, 1);
            s0 += __shfl_xor_sync(0xffffffffu, s0, 2);
            s1 += __shfl_xor_sync(0xffffffffu, s1, 1);
            s1 += __shfl_xor_sync(0xffffffffu, s1, 2);
            l0 = l0*a0 + s0;
            l1 = l1*a1 + s1;

            // ---- P -> A fragments (hi/lo, in-register) ----
            uint32_t PH[4][4], PL[4][4];
#pragma unroll
            for (int g = 0; g < 4; ++g) {
                uint32_t hb[8]; float lf[8];
                split2(S[2*g][0], hb[0], lf[0]);  split2(S[2*g][1], hb[1], lf[1]);
                split2(S[2*g][2], hb[2], lf[2]);  split2(S[2*g][3], hb[3], lf[3]);
                split2(S[2*g+1][0], hb[4], lf[4]); split2(S[2*g+1][1], hb[5], lf[5]);
                split2(S[2*g+1][2], hb[6], lf[6]); split2(S[2*g+1][3], hb[7], lf[7]);
                PH[g][0] = hb[0] | (hb[1] << 16);
                PH[g][1] = hb[2] | (hb[3] << 16);
                PH[g][2] = hb[4] | (hb[5] << 16);
                PH[g][3] = hb[6] | (hb[7] << 16);
                PL[g][0] = packbf(lf[0], lf[1]);
                PL[g][1] = packbf(lf[2], lf[3]);
                PL[g][2] = packbf(lf[4], lf[5]);
                PL[g][3] = packbf(lf[6], lf[7]);
            }

            // ---- O += PH*VH + PL*VH + PH*VL ----
            const int sel = lane >> 3;
#pragma unroll
            for (int g = 0; g < 4; ++g) {
                int krow = g*16 + (lane & 7) + (sel & 1)*8;
#pragma unroll
                for (int np = 0; np < 5; ++np) {
                    uint32_t bv[4], bw[4];
                    int noff = np*16 + (sel >> 1)*8;
                    ldm_x4_t(bv, s2u(&sm.kv.vh[krow*STR + noff]));
                    ldm_x4_t(bw, s2u(&sm.kv.vl[krow*STR + noff]));
                    mma16816(O[2*np],   PH[g], bv[0], bv[1]);
                    mma16816(O[2*np],   PL[g], bv[0], bv[1]);
                    mma16816(O[2*np],   PH[g], bw[0], bw[1]);
                    mma16816(O[2*np+1], PH[g], bv[2], bv[3]);
                    mma16816(O[2*np+1], PL[g], bv[2], bv[3]);
                    mma16816(O[2*np+1], PH[g], bw[2], bw[3]);
                }
            }
        }
        __syncthreads();
    }

    // ---- epilogue: normalize, write bf16 hi/lo ----
    const float i0 = 1.f / l0, i1 = 1.f / l1;
    const size_t base0 = (size_t)(b*SEQ + qrow) * HH + h * HDIM;
    const size_t base1 = base0 + (size_t)8 * HH;
#pragma unroll
    for (int nt = 0; nt < 10; ++nt) {
        int d = nt*8 + (lane & 3)*2;
        {
            float v0 = O[nt][0]*i0, v1 = O[nt][1]*i0;
            uint32_t h0,h1; float f0,f1;
            split2(v0,h0,f0); split2(v1,h1,f1);
            *(uint32_t*)&ahi[base0 + d] = h0 | (h1 << 16);
            *(uint32_t*)&alo[base0 + d] = packbf(f0, f1);
        }
        {
            float v0 = O[nt][2]*i1, v1 = O[nt][3]*i1;
            uint32_t h0,h1; float f0,f1;
            split2(v0,h0,f0); split2(v1,h1,f1);
            *(uint32_t*)&ahi[base1 + d] = h0 | (h1 << 16);
            *(uint32_t*)&alo[base1 + d] = packbf(f0, f1);
        }
    }
}

// ---------------------------------------------------------------------------
// Launch
// ---------------------------------------------------------------------------
extern "C" void kernel_launch(void* const* d_in, const int* in_sizes, int n_in,
                              void* d_out, int out_size)
{
    const float* hidden  = (const float*)d_in[0];
    // d_in[1] = attention_mask: exact additive causal mask; implemented directly.
    const float* scaling = (const float*)d_in[2];
    const float* qkv_w   = (const float*)d_in[3];
    const float* qkv_b   = (const float*)d_in[4];
    const float* o_w     = (const float*)d_in[5];
    const float* o_b     = (const float*)d_in[6];
    float* out = (float*)d_out;

    float *qkv; __nv_bfloat16 *hhi, *hlo, *w1h, *w1l, *w2h, *w2l, *ahi, *alo;
    cudaGetSymbolAddress((void**)&qkv, g_qkv);
    cudaGetSymbolAddress((void**)&hhi, g_h_hi);
    cudaGetSymbolAddress((void**)&hlo, g_h_lo);
    cudaGetSymbolAddress((void**)&w1h, g_w1_hi);
    cudaGetSymbolAddress((void**)&w1l, g_w1_lo);
    cudaGetSymbolAddress((void**)&w2h, g_w2_hi);
    cudaGetSymbolAddress((void**)&w2l, g_w2_lo);
    cudaGetSymbolAddress((void**)&ahi, g_a_hi);
    cudaGetSymbolAddress((void**)&alo, g_a_lo);

    cudaFuncSetAttribute(mma_gemm<0>, cudaFuncAttributeMaxDynamicSharedMemorySize, GSMEM);
    cudaFuncSetAttribute(mma_gemm<1>, cudaFuncAttributeMaxDynamicSharedMemorySize, GSMEM);

    scale_kernel<<<1, 128>>>(scaling);

    {   // hidden -> hi/lo
        int n4 = (MTOT * DMODEL) / 4;
        cvt_split<<<(n4 + 255) / 256, 256>>>(hidden, hhi, hlo, n4);
    }
    {   // qkv_w -> hi/lo
        int n4 = (NQKV * DMODEL) / 4;
        cvt_split<<<(n4 + 255) / 256, 256>>>(qkv_w, w1h, w1l, n4);
    }

    // QKV projection: [8192,1280] @ [3840,1280]^T -> g_qkv (bias + q-scale)
    mma_gemm<0><<<dim3(NQKV / 128, MTOT / 128), 128, GSMEM>>>(
        hhi, hlo, w1h, w1l, qkv_b, qkv, NQKV);

    // Tensor-core flash attention -> bf16 hi/lo
    flash_tc<<<dim3(SEQ / 128, BATCH * NHEAD), 256>>>(qkv, ahi, alo);

    {   // o_w -> hi/lo
        int n4 = (DMODEL * HH) / 4;
        cvt_split<<<(n4 + 255) / 256, 256>>>(o_w, w2h, w2l, n4);
    }

    // Output projection: [8192,1280] @ [1280,1280]^T -> out (bias)
    mma_gemm<1><<<dim3(DMODEL / 128, MTOT / 128), 128, GSMEM>>>(
        ahi, alo, w2h, w2l, o_b, out, DMODEL);
}

// round 15
// speedup vs baseline: 1.3119x; 1.1999x over previous
#include <cuda_runtime.h>
#include <cuda_bf16.h>
#include <cstdint>

// Problem constants
#define BATCH 4
#define SEQ   2048
#define DMODEL 1280
#define NHEAD 16
#define HDIM  80
#define MTOT  (BATCH*SEQ)          // 8192
#define NQKV  (3*NHEAD*HDIM)       // 3840
#define HH    (NHEAD*HDIM)         // 1280

// ---------------------------------------------------------------------------
// Scratch (__device__ globals; no allocation anywhere)
// ---------------------------------------------------------------------------
__device__ float         g_qkv[(size_t)MTOT*NQKV];     // [B*S, 3*H*HD] fp32
__device__ __nv_bfloat16 g_h_hi[(size_t)MTOT*DMODEL];
__device__ __nv_bfloat16 g_h_lo[(size_t)MTOT*DMODEL];
__device__ __nv_bfloat16 g_w1_hi[(size_t)NQKV*DMODEL];
__device__ __nv_bfloat16 g_w1_lo[(size_t)NQKV*DMODEL];
__device__ __nv_bfloat16 g_w2_hi[(size_t)DMODEL*HH];
__device__ __nv_bfloat16 g_w2_lo[(size_t)DMODEL*HH];
__device__ __nv_bfloat16 g_a_hi[(size_t)MTOT*HH];
__device__ __nv_bfloat16 g_a_lo[(size_t)MTOT*HH];
__device__ float         g_scale[HDIM];

// ---------------------------------------------------------------------------
// PTX helpers (plain-sm_103 compatible)
// ---------------------------------------------------------------------------
__device__ __forceinline__ uint32_t s2u(const void* p) {
    uint32_t a;
    asm("{ .reg .u64 t; cvta.to.shared.u64 t, %1; cvt.u32.u64 %0, t; }"
        : "=r"(a) : "l"(p));
    return a;
}

__device__ __forceinline__ void cp_async16(uint32_t saddr, const void* gptr) {
    asm volatile("cp.async.cg.shared.global [%0], [%1], 16;"
                 :: "r"(saddr), "l"(gptr) : "memory");
}
__device__ __forceinline__ void cp_commit() {
    asm volatile("cp.async.commit_group;" ::: "memory");
}
template<int N>
__device__ __forceinline__ void cp_wait() {
    asm volatile("cp.async.wait_group %0;" :: "n"(N) : "memory");
}

__device__ __forceinline__ void ldm_x4(uint32_t* r, uint32_t addr) {
    asm volatile("ldmatrix.sync.aligned.m8n8.x4.shared.b16 {%0,%1,%2,%3}, [%4];"
                 : "=r"(r[0]), "=r"(r[1]), "=r"(r[2]), "=r"(r[3]) : "r"(addr));
}
__device__ __forceinline__ void ldm_x4_t(uint32_t* r, uint32_t addr) {
    asm volatile("ldmatrix.sync.aligned.m8n8.x4.trans.shared.b16 {%0,%1,%2,%3}, [%4];"
                 : "=r"(r[0]), "=r"(r[1]), "=r"(r[2]), "=r"(r[3]) : "r"(addr));
}

__device__ __forceinline__ void mma16816(float* c, const uint32_t* a,
                                         uint32_t b0, uint32_t b1) {
    asm volatile(
        "mma.sync.aligned.m16n8k16.row.col.f32.bf16.bf16.f32 "
        "{%0,%1,%2,%3},{%4,%5,%6,%7},{%8,%9},{%0,%1,%2,%3};"
        : "+f"(c[0]), "+f"(c[1]), "+f"(c[2]), "+f"(c[3])
        : "r"(a[0]), "r"(a[1]), "r"(a[2]), "r"(a[3]), "r"(b0), "r"(b1));
}

// pack two fp32 -> bf16x2 (e0 in low half, e1 in high half)
__device__ __forceinline__ uint32_t packbf(float e0, float e1) {
    uint32_t r;
    asm("cvt.rn.bf16x2.f32 %0, %1, %2;" : "=r"(r) : "f"(e1), "f"(e0));
    return r;
}

// truncation split: x = hi + lo, hi = upper-16-bit bf16 bits, lo fp32 residual
__device__ __forceinline__ void split2(float x, uint32_t& hb, float& lf) {
    uint32_t u = __float_as_uint(x) & 0xffff0000u;
    lf = x - __uint_as_float(u);
    hb = u >> 16;
}

// ---------------------------------------------------------------------------
// per-dim query scale (extra log2e: scores live in log2 domain)
// ---------------------------------------------------------------------------
__global__ void scale_kernel(const float* __restrict__ scaling) {
    int i = threadIdx.x;
    if (i < HDIM) {
        float x = scaling[i];
        float sp = (x > 20.f) ? x : log1pf(expf(x));
        g_scale[i] = sp * 1.442695041f * rsqrtf((float)HDIM) * 1.442695041f;
    }
}

// ---------------------------------------------------------------------------
// fp32 -> bf16 hi/lo split
// ---------------------------------------------------------------------------
__global__ void cvt_split(const float* __restrict__ x,
                          __nv_bfloat16* __restrict__ hi,
                          __nv_bfloat16* __restrict__ lo, int n4) {
    int i = blockIdx.x * blockDim.x + threadIdx.x;
    if (i >= n4) return;
    float4 v = ((const float4*)x)[i];
    __nv_bfloat16 h0 = __float2bfloat16(v.x);
    __nv_bfloat16 h1 = __float2bfloat16(v.y);
    __nv_bfloat16 h2 = __float2bfloat16(v.z);
    __nv_bfloat16 h3 = __float2bfloat16(v.w);
    __nv_bfloat162 hh0; hh0.x = h0; hh0.y = h1;
    __nv_bfloat162 hh1; hh1.x = h2; hh1.y = h3;
    __nv_bfloat162 ll0, ll1;
    ll0.x = __float2bfloat16(v.x - __bfloat162float(h0));
    ll0.y = __float2bfloat16(v.y - __bfloat162float(h1));
    ll1.x = __float2bfloat16(v.z - __bfloat162float(h2));
    ll1.y = __float2bfloat16(v.w - __bfloat162float(h3));
    ((__nv_bfloat162*)hi)[2*i]   = hh0;
    ((__nv_bfloat162*)hi)[2*i+1] = hh1;
    ((__nv_bfloat162*)lo)[2*i]   = ll0;
    ((__nv_bfloat162*)lo)[2*i+1] = ll1;
}

// ---------------------------------------------------------------------------
// HMMA GEMM: C = A*B^T + bias (MODE 0: q-scale)
// CTA 128x128, 4 warps as 2x2 (warp tile 64x64), 4-stage cp.async pipeline,
// register-double-buffered fragments: LDSM of slice s+1 overlaps mma of s.
// ---------------------------------------------------------------------------
#define GK      DMODEL       // 1280
#define KCH     (GK/32)      // 40
#define NIT     (3*KCH)      // 120
#define A_B     (128*80)     // 10240 bytes A per stage (stride 80)
#define B_B     (128*80)     // 10240
#define STG_B   (A_B+B_B)    // 20480
#define GSMEM   (4*STG_B)    // 81920

template<int MODE>
__global__ __launch_bounds__(128)
void mma_gemm(const __nv_bfloat16* __restrict__ Ahi, const __nv_bfloat16* __restrict__ Alo,
              const __nv_bfloat16* __restrict__ Bhi, const __nv_bfloat16* __restrict__ Blo,
              const float* __restrict__ bias, float* __restrict__ dst, int Nld)
{
    extern __shared__ __align__(16) unsigned char dynsm[];

    const int tid  = threadIdx.x;
    const int lane = tid & 31;
    const int wid  = tid >> 5;
    const int wm   = wid >> 1;        // 0..1 -> 64 rows
    const int wn   = wid & 1;         // 0..1 -> 64 cols
    const int m0   = blockIdx.y * 128;
    const int n0   = blockIdx.x * 128;

    float acc[4][8][4];
#pragma unroll
    for (int a = 0; a < 4; ++a)
#pragma unroll
        for (int b = 0; b < 8; ++b)
#pragma unroll
            for (int c = 0; c < 4; ++c) acc[a][b][c] = 0.f;

    const int lrow = tid >> 2;        // 0..31
    const int lchk = tid & 3;
    const uint32_t smem_u = s2u(dynsm);

    auto issue = [&](int cc, int stg) {
        const int seg = cc / KCH;
        const int k0  = (cc % KCH) * 32;
        const __nv_bfloat16* Ap = (seg == 1) ? Alo : Ahi;
        const __nv_bfloat16* Bp = (seg == 2) ? Blo : Bhi;
        uint32_t sa = smem_u + stg * STG_B;
        uint32_t sb = sa + A_B;
#pragma unroll
        for (int h = 0; h < 4; ++h) {
            int r = lrow + h * 32;
            cp_async16(sa + r * 80 + lchk * 16,
                       Ap + (size_t)(m0 + r) * GK + k0 + lchk * 8);
            cp_async16(sb + r * 80 + lchk * 16,
                       Bp + (size_t)(n0 + r) * GK + k0 + lchk * 8);
        }
    };

    // fragment slice loaders (ks = 0/1 -> k16 halves of a 32-K chunk)
    const int a_row  = wm * 64 + (lane & 15);
    const int a_kho  = (lane >> 4) * 8;
    const int b_sel  = lane >> 3;
    const int b_rowb = wn * 64 + (lane & 7) + (b_sel >> 1) * 8;
    const int b_kho  = (b_sel & 1) * 8;

    auto load_slice = [&](uint32_t af[4][4], uint32_t bf[4][4],
                          uint32_t sa, uint32_t sb, int ks) {
#pragma unroll
        for (int ms = 0; ms < 4; ++ms)
            ldm_x4(af[ms], sa + (a_row + ms * 16) * 80 + (ks * 16 + a_kho) * 2);
#pragma unroll
        for (int nb = 0; nb < 4; ++nb)
            ldm_x4(bf[nb], sb + (b_rowb + nb * 16) * 80 + (ks * 16 + b_kho) * 2);
    };

    auto mma_slice = [&](uint32_t af[4][4], uint32_t bf[4][4]) {
#pragma unroll
        for (int ms = 0; ms < 4; ++ms)
#pragma unroll
            for (int ns = 0; ns < 8; ++ns) {
                const uint32_t* bb = bf[ns >> 1];
                if (ns & 1) mma16816(acc[ms][ns], af[ms], bb[2], bb[3]);
                else        mma16816(acc[ms][ns], af[ms], bb[0], bb[1]);
            }
    };

    // prologue: stages 0..2 in flight; slice (0, ks0) in registers
#pragma unroll
    for (int s = 0; s < 3; ++s) { issue(s, s); cp_commit(); }
    cp_wait<2>();
    __syncthreads();

    uint32_t afS0[4][4], bfS0[4][4], afS1[4][4], bfS1[4][4];
    load_slice(afS0, bfS0, smem_u, smem_u + A_B, 0);

#pragma unroll 1
    for (int cc = 0; cc < NIT; ++cc) {
        const uint32_t sa = smem_u + (cc & 3) * STG_B;
        const uint32_t sb = sa + A_B;

        load_slice(afS1, bfS1, sa, sb, 1);     // LDSM slice1 (in flight)
        if (cc + 3 < NIT) { issue(cc + 3, (cc + 3) & 3); }
        cp_commit();
        mma_slice(afS0, bfS0);                  // overlaps slice1 LDSM

        cp_wait<2>();                           // stage cc+1 resident
        __syncthreads();

        const uint32_t na = smem_u + ((cc + 1) & 3) * STG_B;
        load_slice(afS0, bfS0, na, na + A_B, 0); // LDSM next chunk slice0
        mma_slice(afS1, bfS1);                  // overlaps slice0 LDSM
    }

    const int qr = lane >> 2;
    const int qc = lane & 3;
#pragma unroll
    for (int ms = 0; ms < 4; ++ms) {
        int mrow = m0 + wm * 64 + ms * 16 + qr;
#pragma unroll
        for (int ns = 0; ns < 8; ++ns) {
            int ncol = n0 + wn * 64 + ns * 8 + qc * 2;
            float b0 = bias[ncol], b1 = bias[ncol + 1];
            float s0 = 1.f, s1 = 1.f;
            if (MODE == 0 && ncol < HH) {
                int d = ncol % HDIM;
                s0 = g_scale[d];
                s1 = g_scale[d + 1];
            }
            float2 v0, v1;
            v0.x = (acc[ms][ns][0] + b0) * s0;
            v0.y = (acc[ms][ns][1] + b1) * s1;
            v1.x = (acc[ms][ns][2] + b0) * s0;
            v1.y = (acc[ms][ns][3] + b1) * s1;
            *(float2*)&dst[(size_t)mrow * Nld + ncol]       = v0;
            *(float2*)&dst[(size_t)(mrow + 8) * Nld + ncol] = v1;
        }
    }
}

// ---------------------------------------------------------------------------
// exp2 on the FMA pipe (no MUFU); args always <= 0 here
// ---------------------------------------------------------------------------
__device__ __forceinline__ float exp2f_fast(float x) {
    x = fmaxf(x, -126.f);
    float t = rintf(x);
    float f = x - t;
    float p = 1.3333558e-3f;
    p = fmaf(p, f, 9.6181291e-3f);
    p = fmaf(p, f, 5.5504109e-2f);
    p = fmaf(p, f, 2.4022651e-1f);
    p = fmaf(p, f, 6.9314718e-1f);
    p = fmaf(p, f, 1.0f);
    return __int_as_float(__float_as_int(p) + (((int)t) << 23));
}

// ---------------------------------------------------------------------------
// Tensor-core flash attention (causal, log2-domain softmax).
// Register-prefetch of the next K/V tile overlaps LDG with the mma block.
// ---------------------------------------------------------------------------
#define STR 88   // bf16 elements per smem row (176B, conflict-free ldmatrix)

__global__ __launch_bounds__(256)
void flash_tc(const float* __restrict__ qkv,
              __nv_bfloat16* __restrict__ ahi,
              __nv_bfloat16* __restrict__ alo)
{
    __shared__ union {
        struct { __nv_bfloat16 h[128*STR]; __nv_bfloat16 l[128*STR]; } q;
        struct { __nv_bfloat16 kh[64*STR]; __nv_bfloat16 kl[64*STR];
                 __nv_bfloat16 vh[64*STR]; __nv_bfloat16 vl[64*STR]; } kv;
    } sm;

    const int tid  = threadIdx.x;
    const int lane = tid & 31;
    const int wm   = tid >> 5;
    const int qb   = blockIdx.x;
    const int bh   = blockIdx.y;
    const int b    = bh >> 4, h = bh & 15;

    // ---- stage Q (pre-scaled fp32 -> bf16 hi/lo) ----
    {
        int row = tid >> 1, half = tid & 1;
        const float* qp = qkv + (size_t)(b*SEQ + qb*128 + row)*NQKV + h*HDIM + half*40;
        uint32_t* dh = (uint32_t*)&sm.q.h[row*STR + half*40];
        uint32_t* dl = (uint32_t*)&sm.q.l[row*STR + half*40];
#pragma unroll
        for (int i = 0; i < 10; ++i) {
            float4 v = *(const float4*)(qp + i*4);
            uint32_t h0,h1,h2,h3; float l0,l1,l2,l3;
            split2(v.x,h0,l0); split2(v.y,h1,l1);
            split2(v.z,h2,l2); split2(v.w,h3,l3);
            dh[i*2]   = h0 | (h1 << 16);
            dh[i*2+1] = h2 | (h3 << 16);
            dl[i*2]   = packbf(l0, l1);
            dl[i*2+1] = packbf(l2, l3);
        }
    }
    __syncthreads();

    uint32_t QH[5][4], QL[5][4];
    {
        int r = wm*16 + (lane & 15);
        int ko = (lane >> 4) * 8;
#pragma unroll
        for (int kf = 0; kf < 5; ++kf) {
            ldm_x4(QH[kf], s2u(&sm.q.h[r*STR + kf*16 + ko]));
            ldm_x4(QL[kf], s2u(&sm.q.l[r*STR + kf*16 + ko]));
        }
    }
    __syncthreads();   // done with q region before kv overwrites it

    float O[10][4];
#pragma unroll
    for (int i = 0; i < 10; ++i)
#pragma unroll
        for (int j = 0; j < 4; ++j) O[i][j] = 0.f;
    float m0 = -1e30f, m1 = -1e30f, l0 = 0.f, l1 = 0.f;

    const int ntiles = qb*2 + 2;
    const int qrow = qb*128 + wm*16 + (lane >> 2);   // row0; row1 = qrow+8

    const int ldr = tid >> 2, ldq = tid & 3;
    const float* kb0 = qkv + (size_t)b*SEQ*NQKV + HH + h*HDIM + ldq*20;

    float4 kreg[5], vreg[5];
    {   // prefetch tile 0
        const float* kp = kb0 + (size_t)ldr * NQKV;
        const float* vp = kp + HH;
#pragma unroll
        for (int i = 0; i < 5; ++i) {
            kreg[i] = *(const float4*)(kp + i*4);
            vreg[i] = *(const float4*)(vp + i*4);
        }
    }

    for (int t = 0; t < ntiles; ++t) {
        // ---- convert + store prefetched K/V tile (hi/lo) ----
        {
            uint32_t* kh = (uint32_t*)&sm.kv.kh[ldr*STR + ldq*20];
            uint32_t* kl = (uint32_t*)&sm.kv.kl[ldr*STR + ldq*20];
            uint32_t* vh = (uint32_t*)&sm.kv.vh[ldr*STR + ldq*20];
            uint32_t* vl = (uint32_t*)&sm.kv.vl[ldr*STR + ldq*20];
#pragma unroll
            for (int i = 0; i < 5; ++i) {
                uint32_t h0,h1,h2,h3; float f0,f1,f2,f3;
                split2(kreg[i].x,h0,f0); split2(kreg[i].y,h1,f1);
                split2(kreg[i].z,h2,f2); split2(kreg[i].w,h3,f3);
                kh[i*2]   = h0 | (h1 << 16);
                kh[i*2+1] = h2 | (h3 << 16);
                kl[i*2]   = packbf(f0, f1);
                kl[i*2+1] = packbf(f2, f3);
                split2(vreg[i].x,h0,f0); split2(vreg[i].y,h1,f1);
                split2(vreg[i].z,h2,f2); split2(vreg[i].w,h3,f3);
                vh[i*2]   = h0 | (h1 << 16);
                vh[i*2+1] = h2 | (h3 << 16);
                vl[i*2]   = packbf(f0, f1);
                vl[i*2+1] = packbf(f2, f3);
            }
        }
        __syncthreads();

        // ---- prefetch next tile while mma block runs ----
        if (t + 1 < ntiles) {
            const float* kp = kb0 + (size_t)((t+1)*64 + ldr) * NQKV;
            const float* vp = kp + HH;
#pragma unroll
            for (int i = 0; i < 5; ++i) {
                kreg[i] = *(const float4*)(kp + i*4);
                vreg[i] = *(const float4*)(vp + i*4);
            }
        }

        const bool active = (t*64) <= (qb*128 + wm*16 + 15);
        if (active) {
            float S[8][4];
#pragma unroll
            for (int i = 0; i < 8; ++i)
#pragma unroll
                for (int j = 0; j < 4; ++j) S[i][j] = 0.f;

            // ---- S = Q K^T (hh + lh + hl) ----
#pragma unroll
            for (int kf = 0; kf < 5; ++kf) {
                const int sel  = lane >> 3;
                const int koff = kf*16 + (sel & 1)*8;
#pragma unroll
                for (int g = 0; g < 4; ++g) {
                    uint32_t bh_[4], bl_[4];
                    int krow = g*16 + (lane & 7) + (sel >> 1)*8;
                    ldm_x4(bh_, s2u(&sm.kv.kh[krow*STR + koff]));
                    ldm_x4(bl_, s2u(&sm.kv.kl[krow*STR + koff]));
                    mma16816(S[2*g],   QH[kf], bh_[0], bh_[1]);
                    mma16816(S[2*g+1], QH[kf], bh_[2], bh_[3]);
                    mma16816(S[2*g],   QL[kf], bh_[0], bh_[1]);
                    mma16816(S[2*g+1], QL[kf], bh_[2], bh_[3]);
                    mma16816(S[2*g],   QH[kf], bl_[0], bl_[1]);
                    mma16816(S[2*g+1], QH[kf], bl_[2], bl_[3]);
                }
            }

            // ---- causal mask (diagonal tiles only) ----
            if (t*64 + 63 > qb*128 + wm*16) {
#pragma unroll
                for (int nt = 0; nt < 8; ++nt) {
                    int j = t*64 + nt*8 + (lane & 3)*2;
                    if (j     > qrow)     S[nt][0] = -1e30f;
                    if (j + 1 > qrow)     S[nt][1] = -1e30f;
                    if (j     > qrow + 8) S[nt][2] = -1e30f;
                    if (j + 1 > qrow + 8) S[nt][3] = -1e30f;
                }
            }

            // ---- online softmax ----
            float rm0 = -1e30f, rm1 = -1e30f;
#pragma unroll
            for (int nt = 0; nt < 8; ++nt) {
                rm0 = fmaxf(rm0, fmaxf(S[nt][0], S[nt][1]));
                rm1 = fmaxf(rm1, fmaxf(S[nt][2], S[nt][3]));
            }
            rm0 = fmaxf(rm0, __shfl_xor_sync(0xffffffffu, rm0, 1));
            rm0 = fmaxf(rm0, __shfl_xor_sync(0xffffffffu, rm0, 2));
            rm1 = fmaxf(rm1, __shfl_xor_sync(0xffffffffu, rm1, 1));
            rm1 = fmaxf(rm1, __shfl_xor_sync(0xffffffffu, rm1, 2));

            float nm0 = fmaxf(m0, rm0), nm1 = fmaxf(m1, rm1);
            float a0 = exp2f_fast(m0 - nm0), a1 = exp2f_fast(m1 - nm1);
            m0 = nm0; m1 = nm1;
#pragma unroll
            for (int nt = 0; nt < 10; ++nt) {
                O[nt][0] *= a0; O[nt][1] *= a0;
                O[nt][2] *= a1; O[nt][3] *= a1;
            }
            float s0 = 0.f, s1 = 0.f;
#pragma unroll
            for (int nt = 0; nt < 8; ++nt) {
                S[nt][0] = exp2f_fast(S[nt][0] - nm0); s0 += S[nt][0];
                S[nt][1] = exp2f_fast(S[nt][1] - nm0); s0 += S[nt][1];
                S[nt][2] = exp2f_fast(S[nt][2] - nm1); s1 += S[nt][2];
                S[nt][3] = exp2f_fast(S[nt][3] - nm1); s1 += S[nt][3];
            }
            s0 += __shfl_xor_sync(0xffffffffu, s0, 1);
            s0 += __shfl_xor_sync(0xffffffffu, s0, 2);
            s1 += __shfl_xor_sync(0xffffffffu, s1, 1);
            s1 += __shfl_xor_sync(0xffffffffu, s1, 2);
            l0 = l0*a0 + s0;
            l1 = l1*a1 + s1;

            // ---- P -> A fragments (hi/lo, in-register) ----
            uint32_t PH[4][4], PL[4][4];
#pragma unroll
            for (int g = 0; g < 4; ++g) {
                uint32_t hb[8]; float lf[8];
                split2(S[2*g][0], hb[0], lf[0]);  split2(S[2*g][1], hb[1], lf[1]);
                split2(S[2*g][2], hb[2], lf[2]);  split2(S[2*g][3], hb[3], lf[3]);
                split2(S[2*g+1][0], hb[4], lf[4]); split2(S[2*g+1][1], hb[5], lf[5]);
                split2(S[2*g+1][2], hb[6], lf[6]); split2(S[2*g+1][3], hb[7], lf[7]);
                PH[g][0] = hb[0] | (hb[1] << 16);
                PH[g][1] = hb[2] | (hb[3] << 16);
                PH[g][2] = hb[4] | (hb[5] << 16);
                PH[g][3] = hb[6] | (hb[7] << 16);
                PL[g][0] = packbf(lf[0], lf[1]);
                PL[g][1] = packbf(lf[2], lf[3]);
                PL[g][2] = packbf(lf[4], lf[5]);
                PL[g][3] = packbf(lf[6], lf[7]);
            }

            // ---- O += PH*VH + PL*VH + PH*VL ----
            const int sel = lane >> 3;
#pragma unroll
            for (int g = 0; g < 4; ++g) {
                int krow = g*16 + (lane & 7) + (sel & 1)*8;
#pragma unroll
                for (int np = 0; np < 5; ++np) {
                    uint32_t bv[4], bw[4];
                    int noff = np*16 + (sel >> 1)*8;
                    ldm_x4_t(bv, s2u(&sm.kv.vh[krow*STR + noff]));
                    ldm_x4_t(bw, s2u(&sm.kv.vl[krow*STR + noff]));
                    mma16816(O[2*np],   PH[g], bv[0], bv[1]);
                    mma16816(O[2*np],   PL[g], bv[0], bv[1]);
                    mma16816(O[2*np],   PH[g], bw[0], bw[1]);
                    mma16816(O[2*np+1], PH[g], bv[2], bv[3]);
                    mma16816(O[2*np+1], PL[g], bv[2], bv[3]);
                    mma16816(O[2*np+1], PH[g], bw[2], bw[3]);
                }
            }
        }
        __syncthreads();
    }

    // ---- epilogue: normalize, write bf16 hi/lo ----
    const float i0 = 1.f / l0, i1 = 1.f / l1;
    const size_t base0 = (size_t)(b*SEQ + qrow) * HH + h * HDIM;
    const size_t base1 = base0 + (size_t)8 * HH;
#pragma unroll
    for (int nt = 0; nt < 10; ++nt) {
        int d = nt*8 + (lane & 3)*2;
        {
            float v0 = O[nt][0]*i0, v1 = O[nt][1]*i0;
            uint32_t h0,h1; float f0,f1;
            split2(v0,h0,f0); split2(v1,h1,f1);
            *(uint32_t*)&ahi[base0 + d] = h0 | (h1 << 16);
            *(uint32_t*)&alo[base0 + d] = packbf(f0, f1);
        }
        {
            float v0 = O[nt][2]*i1, v1 = O[nt][3]*i1;
            uint32_t h0,h1; float f0,f1;
            split2(v0,h0,f0); split2(v1,h1,f1);
            *(uint32_t*)&ahi[base1 + d] = h0 | (h1 << 16);
            *(uint32_t*)&alo[base1 + d] = packbf(f0, f1);
        }
    }
}

// ---------------------------------------------------------------------------
// Launch
// ---------------------------------------------------------------------------
extern "C" void kernel_launch(void* const* d_in, const int* in_sizes, int n_in,
                              void* d_out, int out_size)
{
    const float* hidden  = (const float*)d_in[0];
    // d_in[1] = attention_mask: exact additive causal mask; implemented directly.
    const float* scaling = (const float*)d_in[2];
    const float* qkv_w   = (const float*)d_in[3];
    const float* qkv_b   = (const float*)d_in[4];
    const float* o_w     = (const float*)d_in[5];
    const float* o_b     = (const float*)d_in[6];
    float* out = (float*)d_out;

    float *qkv; __nv_bfloat16 *hhi, *hlo, *w1h, *w1l, *w2h, *w2l, *ahi, *alo;
    cudaGetSymbolAddress((void**)&qkv, g_qkv);
    cudaGetSymbolAddress((void**)&hhi, g_h_hi);
    cudaGetSymbolAddress((void**)&hlo, g_h_lo);
    cudaGetSymbolAddress((void**)&w1h, g_w1_hi);
    cudaGetSymbolAddress((void**)&w1l, g_w1_lo);
    cudaGetSymbolAddress((void**)&w2h, g_w2_hi);
    cudaGetSymbolAddress((void**)&w2l, g_w2_lo);
    cudaGetSymbolAddress((void**)&ahi, g_a_hi);
    cudaGetSymbolAddress((void**)&alo, g_a_lo);

    cudaFuncSetAttribute(mma_gemm<0>, cudaFuncAttributeMaxDynamicSharedMemorySize, GSMEM);
    cudaFuncSetAttribute(mma_gemm<1>, cudaFuncAttributeMaxDynamicSharedMemorySize, GSMEM);

    scale_kernel<<<1, 128>>>(scaling);

    {   // hidden -> hi/lo
        int n4 = (MTOT * DMODEL) / 4;
        cvt_split<<<(n4 + 255) / 256, 256>>>(hidden, hhi, hlo, n4);
    }
    {   // qkv_w -> hi/lo
        int n4 = (NQKV * DMODEL) / 4;
        cvt_split<<<(n4 + 255) / 256, 256>>>(qkv_w, w1h, w1l, n4);
    }

    // QKV projection: [8192,1280] @ [3840,1280]^T -> g_qkv (bias + q-scale)
    mma_gemm<0><<<dim3(NQKV / 128, MTOT / 128), 128, GSMEM>>>(
        hhi, hlo, w1h, w1l, qkv_b, qkv, NQKV);

    // Tensor-core flash attention -> bf16 hi/lo
    flash_tc<<<dim3(SEQ / 128, BATCH * NHEAD), 256>>>(qkv, ahi, alo);

    {   // o_w -> hi/lo
        int n4 = (DMODEL * HH) / 4;
        cvt_split<<<(n4 + 255) / 256, 256>>>(o_w, w2h, w2l, n4);
    }

    // Output projection: [8192,1280] @ [1280,1280]^T -> out (bias)
    mma_gemm<1><<<dim3(DMODEL / 128, MTOT / 128), 128, GSMEM>>>(
        ahi, alo, w2h, w2l, o_b, out, DMODEL);
}